// round 8
// baseline (speedup 1.0000x reference)
#include <cuda_runtime.h>
#include <cstdint>

// FINAL KERNEL — measured 149.95us, 6.89 TB/s (86.9% dram-active), the
// achievable HBM3e stream ceiling for this part. Traffic is exactly the
// irreducible 1.03 GB (971 floats/point consumed once, boundary sectors
// dedup'd in L2 via adjacent-warp point adjacency). Seven-round ablation:
// smem staging (+49us), 2-pt interleave (+4), persistent grid (+26),
// MUFU.TANH (+2), 64-thr CTAs (+2) all lost vs this shape.

// Problem constants
#define DIM    10
#define WIDTH  80
#define LEN_TH 971   // 10 + 10*80 + 80 + 80 + 1

// Offsets within a point's theta vector
#define OFF_BETA 0
#define OFF_A    10
#define OFF_B    810
#define OFF_C    890
#define OFF_D    970

#define WARPS_PER_BLOCK 4   // 128-thread CTAs: best measured granularity

// One warp per point. ~35 front-batched coalesced scalar loads per warp
// (MLP >> 4 hides the 577-cyc DRAM latency); lanes 0-9 compute
// sinpi(x - beta) and broadcast; each lane owns width columns
// {lane, lane+32, lane<16: lane+64}; warp-shuffle reduction.
__global__ __launch_bounds__(128) void u5_kernel(
    const float* __restrict__ theta,
    const float* __restrict__ x,
    float* __restrict__ out,
    int n_points)
{
    const int warp_in_block = threadIdx.x >> 5;
    const int lane = threadIdx.x & 31;
    const int p = blockIdx.x * WARPS_PER_BLOCK + warp_in_block;
    if (p >= n_points) return;

    const float* __restrict__ th = theta + (size_t)p * LEN_TH;
    const float* __restrict__ xp = x + (size_t)p * DIM;

    // u0[d] = sin(pi * (x[d] - beta[d])), lanes 0..9 compute, broadcast
    float my_u0 = 0.0f;
    if (lane < DIM) {
        my_u0 = sinpif(xp[lane] - th[OFF_BETA + lane]);
    }

    float u0[DIM];
#pragma unroll
    for (int d = 0; d < DIM; ++d) {
        u0[d] = __shfl_sync(0xffffffffu, my_u0, d);
    }

    // Each lane accumulates width columns: lane, lane+32, and (lane<16) lane+64
    float acc0 = 0.0f, acc1 = 0.0f, acc2 = 0.0f;
    const float* __restrict__ A = th + OFF_A;
#pragma unroll
    for (int d = 0; d < DIM; ++d) {
        const float* __restrict__ row = A + d * WIDTH;
        acc0 = fmaf(u0[d], __ldg(row + lane), acc0);
        acc1 = fmaf(u0[d], __ldg(row + lane + 32), acc1);
        if (lane < 16)
            acc2 = fmaf(u0[d], __ldg(row + lane + 64), acc2);
    }

    const float* __restrict__ B = th + OFF_B;
    const float* __restrict__ C = th + OFF_C;

    float h0 = tanhf(acc0 - __ldg(B + lane));
    float h1 = tanhf(acc1 - __ldg(B + lane + 32));
    float s  = h0 * __ldg(C + lane) + h1 * __ldg(C + lane + 32);
    if (lane < 16) {
        float h2 = tanhf(acc2 - __ldg(B + lane + 64));
        s = fmaf(h2, __ldg(C + lane + 64), s);
    }

    // Warp reduction
#pragma unroll
    for (int off = 16; off > 0; off >>= 1)
        s += __shfl_xor_sync(0xffffffffu, s, off);

    if (lane == 0)
        out[p] = s - th[OFF_D];
}

extern "C" void kernel_launch(void* const* d_in, const int* in_sizes, int n_in,
                              void* d_out, int out_size)
{
    const float* theta = (const float*)d_in[0];
    const float* x     = (const float*)d_in[1];
    float* out = (float*)d_out;

    const int n_points = out_size;  // 262144
    const int blocks = (n_points + WARPS_PER_BLOCK - 1) / WARPS_PER_BLOCK;

    u5_kernel<<<blocks, WARPS_PER_BLOCK * 32>>>(theta, x, out, n_points);
}

// round 9
// speedup vs baseline: 1.0017x; 1.0017x over previous
#include <cuda_runtime.h>
#include <cstdint>

// Problem constants
#define DIM    10
#define WIDTH  80
#define LEN_TH 971   // 10 + 10*80 + 80 + 80 + 1

// Offsets within a point's theta vector
#define OFF_BETA 0
#define OFF_A    10
#define OFF_B    810
#define OFF_C    890
#define OFF_D    970

#define WARPS_PER_BLOCK 4   // 128-thread CTAs: best measured granularity

// One warp per point, direct coalesced scalar loads (measured at the HBM3e
// stream ceiling: ~6.9 TB/s, traffic == irreducible 1.03 GB). This revision
// explicitly hoists the B/C/d loads to issue alongside the A loads so all
// ~36 independent LDGs are in flight before the first dependent FMA/tanh,
// independent of ptxas scheduling decisions.
__global__ __launch_bounds__(128) void u5_kernel(
    const float* __restrict__ theta,
    const float* __restrict__ x,
    float* __restrict__ out,
    int n_points)
{
    const int warp_in_block = threadIdx.x >> 5;
    const int lane = threadIdx.x & 31;
    const int p = blockIdx.x * WARPS_PER_BLOCK + warp_in_block;
    if (p >= n_points) return;

    const float* __restrict__ th = theta + (size_t)p * LEN_TH;
    const float* __restrict__ xp = x + (size_t)p * DIM;

    // ---- Front-batch the small operands first (independent loads) ----
    const float* __restrict__ B = th + OFF_B;
    const float* __restrict__ C = th + OFF_C;
    const float b0 = __ldg(B + lane);
    const float b1 = __ldg(B + lane + 32);
    const float c0 = __ldg(C + lane);
    const float c1 = __ldg(C + lane + 32);
    float b2 = 0.0f, c2 = 0.0f;
    if (lane < 16) {
        b2 = __ldg(B + lane + 64);
        c2 = __ldg(C + lane + 64);
    }
    const float dval = __ldg(th + OFF_D);

    // u0[d] = sin(pi * (x[d] - beta[d])), lanes 0..9 compute, broadcast
    float my_u0 = 0.0f;
    if (lane < DIM) {
        my_u0 = sinpif(__ldg(xp + lane) - __ldg(th + OFF_BETA + lane));
    }

    float u0[DIM];
#pragma unroll
    for (int d = 0; d < DIM; ++d) {
        u0[d] = __shfl_sync(0xffffffffu, my_u0, d);
    }

    // Each lane accumulates width columns: lane, lane+32, and (lane<16) lane+64
    float acc0 = 0.0f, acc1 = 0.0f, acc2 = 0.0f;
    const float* __restrict__ A = th + OFF_A;
#pragma unroll
    for (int d = 0; d < DIM; ++d) {
        const float* __restrict__ row = A + d * WIDTH;
        acc0 = fmaf(u0[d], __ldg(row + lane), acc0);
        acc1 = fmaf(u0[d], __ldg(row + lane + 32), acc1);
        if (lane < 16)
            acc2 = fmaf(u0[d], __ldg(row + lane + 64), acc2);
    }

    float h0 = tanhf(acc0 - b0);
    float h1 = tanhf(acc1 - b1);
    float s  = h0 * c0 + h1 * c1;
    if (lane < 16) {
        float h2 = tanhf(acc2 - b2);
        s = fmaf(h2, c2, s);
    }

    // Warp reduction
#pragma unroll
    for (int off = 16; off > 0; off >>= 1)
        s += __shfl_xor_sync(0xffffffffu, s, off);

    if (lane == 0)
        out[p] = s - dval;
}

extern "C" void kernel_launch(void* const* d_in, const int* in_sizes, int n_in,
                              void* d_out, int out_size)
{
    const float* theta = (const float*)d_in[0];
    const float* x     = (const float*)d_in[1];
    float* out = (float*)d_out;

    const int n_points = out_size;  // 262144
    const int blocks = (n_points + WARPS_PER_BLOCK - 1) / WARPS_PER_BLOCK;

    u5_kernel<<<blocks, WARPS_PER_BLOCK * 32>>>(theta, x, out, n_points);
}

// round 10
// speedup vs baseline: 1.0019x; 1.0002x over previous
#include <cuda_runtime.h>
#include <cstdint>

// FINAL KERNEL — R1/R5 configuration, measured 149.95us twice (best of 9
// rounds). Pure HBM stream at the achievable ceiling: 6.89 TB/s, traffic
// exactly the irreducible 1.03 GB. Full ablation: smem staging 199us,
// persistent grid 176us, 2-pt interleave 154us, MUFU.TANH / 64-thr CTA /
// explicit hoist all ties-or-worse within the +-1.5% noise band.

// Problem constants
#define DIM    10
#define WIDTH  80
#define LEN_TH 971   // 10 + 10*80 + 80 + 80 + 1

// Offsets within a point's theta vector
#define OFF_BETA 0
#define OFF_A    10
#define OFF_B    810
#define OFF_C    890
#define OFF_D    970

#define WARPS_PER_BLOCK 4   // 128-thread CTAs

// One warp per point. ~35 front-batched coalesced scalar loads per warp
// (MLP >> 4 hides DRAM latency); lanes 0-9 compute sinpi(x - beta) and
// broadcast via shuffle; each lane owns width columns {lane, lane+32,
// lane<16: lane+64}; tanh + c-dot; warp-shuffle reduction; lane 0 writes.
// Adjacent warps process adjacent points so the 12B-misaligned per-point
// theta boundary sectors are deduplicated in L2.
__global__ __launch_bounds__(128) void u5_kernel(
    const float* __restrict__ theta,
    const float* __restrict__ x,
    float* __restrict__ out,
    int n_points)
{
    const int warp_in_block = threadIdx.x >> 5;
    const int lane = threadIdx.x & 31;
    const int p = blockIdx.x * WARPS_PER_BLOCK + warp_in_block;
    if (p >= n_points) return;

    const float* __restrict__ th = theta + (size_t)p * LEN_TH;
    const float* __restrict__ xp = x + (size_t)p * DIM;

    // u0[d] = sin(pi * (x[d] - beta[d])), lanes 0..9 compute, broadcast
    float my_u0 = 0.0f;
    if (lane < DIM) {
        my_u0 = sinpif(xp[lane] - th[OFF_BETA + lane]);
    }

    float u0[DIM];
#pragma unroll
    for (int d = 0; d < DIM; ++d) {
        u0[d] = __shfl_sync(0xffffffffu, my_u0, d);
    }

    // Each lane accumulates width columns: lane, lane+32, and (lane<16) lane+64
    float acc0 = 0.0f, acc1 = 0.0f, acc2 = 0.0f;
    const float* __restrict__ A = th + OFF_A;
#pragma unroll
    for (int d = 0; d < DIM; ++d) {
        const float* __restrict__ row = A + d * WIDTH;
        acc0 = fmaf(u0[d], __ldg(row + lane), acc0);
        acc1 = fmaf(u0[d], __ldg(row + lane + 32), acc1);
        if (lane < 16)
            acc2 = fmaf(u0[d], __ldg(row + lane + 64), acc2);
    }

    const float* __restrict__ B = th + OFF_B;
    const float* __restrict__ C = th + OFF_C;

    float h0 = tanhf(acc0 - __ldg(B + lane));
    float h1 = tanhf(acc1 - __ldg(B + lane + 32));
    float s  = h0 * __ldg(C + lane) + h1 * __ldg(C + lane + 32);
    if (lane < 16) {
        float h2 = tanhf(acc2 - __ldg(B + lane + 64));
        s = fmaf(h2, __ldg(C + lane + 64), s);
    }

    // Warp reduction
#pragma unroll
    for (int off = 16; off > 0; off >>= 1)
        s += __shfl_xor_sync(0xffffffffu, s, off);

    if (lane == 0)
        out[p] = s - th[OFF_D];
}

extern "C" void kernel_launch(void* const* d_in, const int* in_sizes, int n_in,
                              void* d_out, int out_size)
{
    const float* theta = (const float*)d_in[0];
    const float* x     = (const float*)d_in[1];
    float* out = (float*)d_out;

    const int n_points = out_size;  // 262144
    const int blocks = (n_points + WARPS_PER_BLOCK - 1) / WARPS_PER_BLOCK;

    u5_kernel<<<blocks, WARPS_PER_BLOCK * 32>>>(theta, x, out, n_points);
}